// round 15
// baseline (speedup 1.0000x reference)
#include <cuda_runtime.h>
#include <cuda_bf16.h>
#include <cuda_fp16.h>
#include <cstdint>

// Problem dims — FIXED by the dataset (reference hardcodes them).
#define N_NODES 100000
#define N_EDGES 1600000
#define IN_C    128
#define HID_C   128
#define OUT_C   40

#define WPB     16    // nodes (=warps) per block in fused agg kernel (100000%16==0)
#define APAD    132   // padded as row stride -> conflict-free A frags
#define GEMM1_BLOCKS ((N_NODES + 127) / 128)   // 782
#define CAP     96    // bucket capacity per node (P(deg>=96) < 1e-40)

// ---------------- scratch (static __device__ globals; no allocation) --------
__device__ __half    g_h1h[(size_t)N_NODES * HID_C]; // 25.6 MB: x @ W1 (fp16)
__device__ __half    g_th [(size_t)N_NODES * OUT_C]; // 8 MB: layer-2 proj (fp16)
__device__ int       g_bkt[(size_t)N_NODES * CAP];   // 38.4 MB: src ids per dst
__device__ int       g_degi[N_NODES];                // in-degree (= fill cursor)
__device__ int       g_dego[N_NODES];                // out-degree
__device__ float     g_iso[N_NODES];                 // out-degree^{-1/2}
__device__ float     g_isi[N_NODES];                 // in-degree^{-1/2}
__device__ uint32_t  g_w1t[IN_C * HID_C];            // 64 KB: W1 as tf32 bits
__device__ int       g_mode;                         // edge dtype

// ---------------- helpers ----------------------------------------------------
__device__ __forceinline__ uint32_t f2tf32(float v) {
    uint32_t r;
    asm("cvt.rna.tf32.f32 %0, %1;" : "=r"(r) : "f"(v));
    return r;
}

// ---------------- zero + dtype probe (fused) ---------------------------------
__global__ void k_zero_detect(const int* __restrict__ w32) {
    int i = blockIdx.x * blockDim.x + threadIdx.x;
    if (i < N_NODES) { g_degi[i] = 0; g_dego[i] = 0; }
    if (i == 0) {
        int oz = 0, ez = 0, ir = 0;
        for (int k = 0; k < 512; k++) {
            int w = w32[k];
            if (w == 0) { if (k & 1) oz++; else ez++; }
            if (w >= 0 && w < N_NODES) ir++;
        }
        int mode;
        if (oz > 240)      mode = 1;   // int64
        else if (ez > 240) mode = 3;   // float64
        else if (ir > 500) mode = 0;   // int32
        else               mode = 2;   // float32
        g_mode = mode;
    }
}

// ---------------- ONE PASS: decode + out-degree histogram + bucket fill ------
__global__ void k_convert_fill(const void* __restrict__ ei) {
    int e = blockIdx.x * blockDim.x + threadIdx.x;
    if (e >= N_EDGES) return;
    const int mode = g_mode;
    long long vs, vd;
    if (mode == 1)      { vs = ((const long long*)ei)[e]; vd = ((const long long*)ei)[N_EDGES + e]; }
    else if (mode == 0) { vs = ((const int*)ei)[e];       vd = ((const int*)ei)[N_EDGES + e]; }
    else if (mode == 2) { vs = (long long)((const float*)ei)[e];  vd = (long long)((const float*)ei)[N_EDGES + e]; }
    else                { vs = (long long)((const double*)ei)[e]; vd = (long long)((const double*)ei)[N_EDGES + e]; }
    int s = (int)vs, d = (int)vd;
    if (s < 0) s = 0; if (s >= N_NODES) s = N_NODES - 1;
    if (d < 0) d = 0; if (d >= N_NODES) d = N_NODES - 1;
    atomicAdd(&g_dego[s], 1);
    int pos = atomicAdd(&g_degi[d], 1);
    if (pos < CAP) g_bkt[(size_t)d * CAP + pos] = s;
}

// ---------------- norms ------------------------------------------------------
__global__ void k_isqrt() {
    int i = blockIdx.x * blockDim.x + threadIdx.x;
    if (i >= N_NODES) return;
    g_iso[i] = rsqrtf((float)max(g_dego[i], 1));
    g_isi[i] = rsqrtf((float)max(g_degi[i], 1));
}

// ---------------- W1 -> tf32 bits (once; side stream, before gemm1) ---------
__global__ void k_prep_w(const float* __restrict__ W) {
    int i = blockIdx.x * blockDim.x + threadIdx.x;
    if (i < IN_C * HID_C) g_w1t[i] = f2tf32(W[i]);
}

// ---------------- GEMM1 (tf32 MMA, no smem): h1 = x @ W1 -> fp16 ------------
// B fragments LDG'd straight from g_w1t (64 KB, L1-resident). 256 thr/block.
__global__ __launch_bounds__(256)
void k_gemm1_tf32(const float* __restrict__ x) {
    const int t = threadIdx.x;
    const int wid = t >> 5;
    const int lane = t & 31;

    const int row0 = blockIdx.x * 128 + wid * 16 + (lane >> 2);
    const int row1 = row0 + 8;
    const int rc0 = min(row0, N_NODES - 1);
    const int rc1 = min(row1, N_NODES - 1);
    const float* __restrict__ xr0 = x + (size_t)rc0 * IN_C + (lane & 3);
    const float* __restrict__ xr1 = x + (size_t)rc1 * IN_C + (lane & 3);

    float acc[16][4];
    #pragma unroll
    for (int n = 0; n < 16; n++)
        #pragma unroll
        for (int c = 0; c < 4; c++) acc[n][c] = 0.f;

    // B fragment base: row k0+(lane&3), col n*8+(lane>>2)
    const uint32_t* __restrict__ bbase = g_w1t + (lane & 3) * HID_C + (lane >> 2);

    #pragma unroll 2
    for (int ks = 0; ks < 16; ks++) {
        const int k0 = ks * 8;
        uint32_t a0 = f2tf32(xr0[k0]);
        uint32_t a1 = f2tf32(xr1[k0]);
        uint32_t a2 = f2tf32(xr0[k0 + 4]);
        uint32_t a3 = f2tf32(xr1[k0 + 4]);
        const uint32_t* bb0 = bbase + k0 * HID_C;
        const uint32_t* bb1 = bb0 + 4 * HID_C;
        #pragma unroll
        for (int n = 0; n < 16; n++) {
            uint32_t b0 = bb0[n * 8];
            uint32_t b1 = bb1[n * 8];
            asm volatile(
                "mma.sync.aligned.m16n8k8.row.col.f32.tf32.tf32.f32 "
                "{%0,%1,%2,%3}, {%4,%5,%6,%7}, {%8,%9}, {%0,%1,%2,%3};"
                : "+f"(acc[n][0]), "+f"(acc[n][1]), "+f"(acc[n][2]), "+f"(acc[n][3])
                : "r"(a0), "r"(a1), "r"(a2), "r"(a3), "r"(b0), "r"(b1));
        }
    }

    const int colb = (lane & 3) * 2;
    #pragma unroll
    for (int n = 0; n < 16; n++) {
        int col = n * 8 + colb;
        if (row0 < N_NODES)
            *reinterpret_cast<__half2*>(g_h1h + (size_t)row0 * HID_C + col) =
                __floats2half2_rn(acc[n][0], acc[n][1]);
        if (row1 < N_NODES)
            *reinterpret_cast<__half2*>(g_h1h + (size_t)row1 * HID_C + col) =
                __floats2half2_rn(acc[n][2], acc[n][3]);
    }
}

// ---------------- FUSED: agg1 (fp16 rows, unroll-4) + relu/norm + MMA GEMM2 -
__global__ __launch_bounds__(WPB * 32)
void k_agg1_gemm2(const float* __restrict__ W2) {
    __shared__ uint32_t W2s[HID_C * OUT_C];        // 20 KB tf32 bits
    __shared__ uint32_t as_f[WPB * APAD];          // 8.25 KB tf32 bits [16][132]

    const int t = threadIdx.x;
    const int wid = t >> 5;
    const int lane = t & 31;
    const int base = blockIdx.x * WPB;

    #pragma unroll
    for (int i = 0; i < (HID_C * OUT_C) / (WPB * 32); i++)
        W2s[i * (WPB * 32) + t] = f2tf32(W2[i * (WPB * 32) + t]);

    // ---- gather phase (all 16 warps; 4 rows in flight) ----
    const int d = base + wid;
    const int* __restrict__ bp = g_bkt + (size_t)d * CAP;
    const int deg = min(g_degi[d], CAP);
    float4 acc0 = make_float4(0.f, 0.f, 0.f, 0.f);
    float4 acc1 = make_float4(0.f, 0.f, 0.f, 0.f);
    float4 acc2 = make_float4(0.f, 0.f, 0.f, 0.f);
    float4 acc3 = make_float4(0.f, 0.f, 0.f, 0.f);
    int j = 0;
    for (; j + 3 < deg; j += 4) {
        int s0 = bp[j], s1 = bp[j + 1], s2 = bp[j + 2], s3 = bp[j + 3];
        float f0 = g_iso[s0], f1 = g_iso[s1], f2 = g_iso[s2], f3 = g_iso[s3];
        uint2 u0 = *(reinterpret_cast<const uint2*>(g_h1h + (size_t)s0 * HID_C) + lane);
        uint2 u1 = *(reinterpret_cast<const uint2*>(g_h1h + (size_t)s1 * HID_C) + lane);
        uint2 u2 = *(reinterpret_cast<const uint2*>(g_h1h + (size_t)s2 * HID_C) + lane);
        uint2 u3 = *(reinterpret_cast<const uint2*>(g_h1h + (size_t)s3 * HID_C) + lane);
        float2 p0 = __half22float2(*reinterpret_cast<__half2*>(&u0.x));
        float2 q0 = __half22float2(*reinterpret_cast<__half2*>(&u0.y));
        float2 p1 = __half22float2(*reinterpret_cast<__half2*>(&u1.x));
        float2 q1 = __half22float2(*reinterpret_cast<__half2*>(&u1.y));
        float2 p2 = __half22float2(*reinterpret_cast<__half2*>(&u2.x));
        float2 q2 = __half22float2(*reinterpret_cast<__half2*>(&u2.y));
        float2 p3 = __half22float2(*reinterpret_cast<__half2*>(&u3.x));
        float2 q3 = __half22float2(*reinterpret_cast<__half2*>(&u3.y));
        acc0.x += f0 * p0.x; acc0.y += f0 * p0.y; acc0.z += f0 * q0.x; acc0.w += f0 * q0.y;
        acc1.x += f1 * p1.x; acc1.y += f1 * p1.y; acc1.z += f1 * q1.x; acc1.w += f1 * q1.y;
        acc2.x += f2 * p2.x; acc2.y += f2 * p2.y; acc2.z += f2 * q2.x; acc2.w += f2 * q2.y;
        acc3.x += f3 * p3.x; acc3.y += f3 * p3.y; acc3.z += f3 * q3.x; acc3.w += f3 * q3.y;
    }
    for (; j < deg; j++) {
        int s0 = bp[j];
        float f0 = g_iso[s0];
        uint2 u0 = *(reinterpret_cast<const uint2*>(g_h1h + (size_t)s0 * HID_C) + lane);
        float2 p0 = __half22float2(*reinterpret_cast<__half2*>(&u0.x));
        float2 q0 = __half22float2(*reinterpret_cast<__half2*>(&u0.y));
        acc0.x += f0 * p0.x; acc0.y += f0 * p0.y; acc0.z += f0 * q0.x; acc0.w += f0 * q0.y;
    }
    acc0.x += acc1.x + acc2.x + acc3.x;
    acc0.y += acc1.y + acc2.y + acc3.y;
    acc0.z += acc1.z + acc2.z + acc3.z;
    acc0.w += acc1.w + acc2.w + acc3.w;

    const float sc = g_iso[d] * g_isi[d];
    as_f[wid * APAD + lane * 4 + 0] = f2tf32(fmaxf(acc0.x, 0.f) * sc);
    as_f[wid * APAD + lane * 4 + 1] = f2tf32(fmaxf(acc0.y, 0.f) * sc);
    as_f[wid * APAD + lane * 4 + 2] = f2tf32(fmaxf(acc0.z, 0.f) * sc);
    as_f[wid * APAD + lane * 4 + 3] = f2tf32(fmaxf(acc0.w, 0.f) * sc);
    __syncthreads();

    // ---- MMA phase (warps 0..4, n-tile = wid) ----
    if (wid < 5) {
        const int nt = wid;
        float c0 = 0.f, c1 = 0.f, c2 = 0.f, c3 = 0.f;
        const uint32_t* __restrict__ ap0 = as_f + (lane >> 2) * APAD + (lane & 3);
        const uint32_t* __restrict__ ap1 = ap0 + 8 * APAD;
        const uint32_t* __restrict__ bb  = W2s + (lane & 3) * OUT_C + nt * 8 + (lane >> 2);
        #pragma unroll
        for (int ks = 0; ks < 16; ks++) {
            const int k0 = ks * 8;
            uint32_t a0 = ap0[k0];
            uint32_t a1 = ap1[k0];
            uint32_t a2 = ap0[k0 + 4];
            uint32_t a3 = ap1[k0 + 4];
            uint32_t b0 = bb[k0 * OUT_C];
            uint32_t b1 = bb[(k0 + 4) * OUT_C];
            asm volatile(
                "mma.sync.aligned.m16n8k8.row.col.f32.tf32.tf32.f32 "
                "{%0,%1,%2,%3}, {%4,%5,%6,%7}, {%8,%9}, {%0,%1,%2,%3};"
                : "+f"(c0), "+f"(c1), "+f"(c2), "+f"(c3)
                : "r"(a0), "r"(a1), "r"(a2), "r"(a3), "r"(b0), "r"(b1));
        }
        const int row0 = base + (lane >> 2);
        const int row1 = row0 + 8;
        const int col = nt * 8 + 2 * (lane & 3);
        *reinterpret_cast<__half2*>(g_th + (size_t)row0 * OUT_C + col) =
            __floats2half2_rn(c0, c1);
        *reinterpret_cast<__half2*>(g_th + (size_t)row1 * OUT_C + col) =
            __floats2half2_rn(c2, c3);
    }
}

// ---------------- gather 2: out[d] = isi[d]*sum g_t[s], 3 nodes/warp, x4 ----
__global__ __launch_bounds__(256)
void k_agg2(float* __restrict__ out) {
    int gw = (blockIdx.x * blockDim.x + threadIdx.x) >> 5;
    int lane = threadIdx.x & 31;
    int sub = lane / 10;                 // 0,1,2 (lanes 30,31 idle)
    int c = lane - sub * 10;             // 4-col chunk 0..9 (uint2 of halfs)
    int d = gw * 3 + sub;
    if (sub >= 3 || d >= N_NODES) return;
    const int* __restrict__ bp = g_bkt + (size_t)d * CAP;
    const int deg = min(g_degi[d], CAP);
    float4 acc0 = make_float4(0.f, 0.f, 0.f, 0.f);
    float4 acc1 = make_float4(0.f, 0.f, 0.f, 0.f);
    float4 acc2 = make_float4(0.f, 0.f, 0.f, 0.f);
    float4 acc3 = make_float4(0.f, 0.f, 0.f, 0.f);
    int j = 0;
    for (; j + 3 < deg; j += 4) {
        int s0 = bp[j], s1 = bp[j + 1], s2 = bp[j + 2], s3 = bp[j + 3];
        uint2 u0 = *(reinterpret_cast<const uint2*>(g_th + (size_t)s0 * OUT_C) + c);
        uint2 u1 = *(reinterpret_cast<const uint2*>(g_th + (size_t)s1 * OUT_C) + c);
        uint2 u2 = *(reinterpret_cast<const uint2*>(g_th + (size_t)s2 * OUT_C) + c);
        uint2 u3 = *(reinterpret_cast<const uint2*>(g_th + (size_t)s3 * OUT_C) + c);
        float2 p0 = __half22float2(*reinterpret_cast<__half2*>(&u0.x));
        float2 q0 = __half22float2(*reinterpret_cast<__half2*>(&u0.y));
        float2 p1 = __half22float2(*reinterpret_cast<__half2*>(&u1.x));
        float2 q1 = __half22float2(*reinterpret_cast<__half2*>(&u1.y));
        float2 p2 = __half22float2(*reinterpret_cast<__half2*>(&u2.x));
        float2 q2 = __half22float2(*reinterpret_cast<__half2*>(&u2.y));
        float2 p3 = __half22float2(*reinterpret_cast<__half2*>(&u3.x));
        float2 q3 = __half22float2(*reinterpret_cast<__half2*>(&u3.y));
        acc0.x += p0.x; acc0.y += p0.y; acc0.z += q0.x; acc0.w += q0.y;
        acc1.x += p1.x; acc1.y += p1.y; acc1.z += q1.x; acc1.w += q1.y;
        acc2.x += p2.x; acc2.y += p2.y; acc2.z += q2.x; acc2.w += q2.y;
        acc3.x += p3.x; acc3.y += p3.y; acc3.z += q3.x; acc3.w += q3.y;
    }
    for (; j < deg; j++) {
        int s0 = bp[j];
        uint2 u0 = *(reinterpret_cast<const uint2*>(g_th + (size_t)s0 * OUT_C) + c);
        float2 p0 = __half22float2(*reinterpret_cast<__half2*>(&u0.x));
        float2 q0 = __half22float2(*reinterpret_cast<__half2*>(&u0.y));
        acc0.x += p0.x; acc0.y += p0.y; acc0.z += q0.x; acc0.w += q0.y;
    }
    float sc = g_isi[d];
    acc0.x = (acc0.x + acc1.x + acc2.x + acc3.x) * sc;
    acc0.y = (acc0.y + acc1.y + acc2.y + acc3.y) * sc;
    acc0.z = (acc0.z + acc1.z + acc2.z + acc3.z) * sc;
    acc0.w = (acc0.w + acc1.w + acc2.w + acc3.w) * sc;
    *reinterpret_cast<float4*>(out + (size_t)d * OUT_C + c * 4) = acc0;
}

// ---------------- launch ----------------------------------------------------
extern "C" void kernel_launch(void* const* d_in, const int* in_sizes, int n_in,
                              void* d_out, int out_size) {
    const float* x  = (const float*)d_in[0];
    const void*  ei = d_in[1];
    const float* W1 = (const float*)d_in[2];
    const float* W2 = (const float*)d_in[3];
    float* out = (float*)d_out;

    // One-time side-stream / event setup (no device memory; capture-legal)
    static cudaStream_t s_side = nullptr;
    static cudaEvent_t ev_fork = nullptr, ev_join = nullptr;
    if (!s_side) {
        cudaStreamCreateWithFlags(&s_side, cudaStreamNonBlocking);
        cudaEventCreateWithFlags(&ev_fork, cudaEventDisableTiming);
        cudaEventCreateWithFlags(&ev_join, cudaEventDisableTiming);
    }

    // Fork: W1 tf32 prep + GEMM1 (x @ W1) on the side stream
    cudaEventRecord(ev_fork, 0);
    cudaStreamWaitEvent(s_side, ev_fork, 0);
    k_prep_w<<<(IN_C * HID_C + 255) / 256, 256, 0, s_side>>>(W1);
    k_gemm1_tf32<<<GEMM1_BLOCKS, 256, 0, s_side>>>(x);
    cudaEventRecord(ev_join, s_side);

    // Main stream: zero+detect -> one-pass decode/histogram/bucket-fill -> norms
    k_zero_detect<<<(N_NODES + 255) / 256, 256>>>((const int*)ei);
    k_convert_fill<<<(N_EDGES + 255) / 256, 256>>>(ei);
    k_isqrt<<<(N_NODES + 255) / 256, 256>>>();

    // Join: fused aggregation needs both h1 and the buckets
    cudaStreamWaitEvent(0, ev_join, 0);

    k_agg1_gemm2<<<N_NODES / WPB, WPB * 32>>>(W2);

    {
        int warps = (N_NODES + 2) / 3;
        int blocks = (warps * 32 + 255) / 256;
        k_agg2<<<blocks, 256>>>(out);
    }
}

// round 16
// speedup vs baseline: 1.0953x; 1.0953x over previous
#include <cuda_runtime.h>
#include <cuda_bf16.h>
#include <cuda_fp16.h>
#include <cstdint>

// Problem dims — FIXED by the dataset (reference hardcodes them).
#define N_NODES 100000
#define N_EDGES 1600000
#define IN_C    128
#define HID_C   128
#define OUT_C   40

#define WPB     16    // nodes (=warps) per block in fused agg kernel (100000%16==0)
#define WPAD    136   // padded W1 row stride (floats) -> conflict-free B frags
#define APAD    132   // padded as row stride -> conflict-free A frags
#define GEMM1_BLOCKS ((N_NODES + 127) / 128)   // 782
#define CAP     96    // bucket capacity per node (P(deg>=96) < 1e-40)

// ---------------- scratch (static __device__ globals; no allocation) --------
__device__ __half g_h1h[(size_t)N_NODES * HID_C]; // 25.6 MB: x @ W1 (fp16)
__device__ __half g_th [(size_t)N_NODES * OUT_C]; // 8 MB: layer-2 proj (fp16)
__device__ int    g_bkt[(size_t)N_NODES * CAP];   // 38.4 MB: src ids per dst
__device__ int    g_degi[N_NODES];                // in-degree (= fill cursor)
__device__ int    g_dego[N_NODES];                // out-degree
__device__ float  g_iso[N_NODES];                 // out-degree^{-1/2}
__device__ float  g_isi[N_NODES];                 // in-degree^{-1/2}
__device__ int    g_mode;                         // edge dtype

// ---------------- helpers ----------------------------------------------------
__device__ __forceinline__ uint32_t f2tf32(float v) {
    uint32_t r;
    asm("cvt.rna.tf32.f32 %0, %1;" : "=r"(r) : "f"(v));
    return r;
}

// ---------------- zero + dtype probe (fused) ---------------------------------
__global__ void k_zero_detect(const int* __restrict__ w32) {
    int i = blockIdx.x * blockDim.x + threadIdx.x;
    if (i < N_NODES) { g_degi[i] = 0; g_dego[i] = 0; }
    if (i == 0) {
        int oz = 0, ez = 0, ir = 0;
        for (int k = 0; k < 512; k++) {
            int w = w32[k];
            if (w == 0) { if (k & 1) oz++; else ez++; }
            if (w >= 0 && w < N_NODES) ir++;
        }
        int mode;
        if (oz > 240)      mode = 1;   // int64
        else if (ez > 240) mode = 3;   // float64
        else if (ir > 500) mode = 0;   // int32
        else               mode = 2;   // float32
        g_mode = mode;
    }
}

// ---------------- ONE PASS: decode + out-degree histogram + bucket fill ------
__global__ void k_convert_fill(const void* __restrict__ ei) {
    int e = blockIdx.x * blockDim.x + threadIdx.x;
    if (e >= N_EDGES) return;
    const int mode = g_mode;
    long long vs, vd;
    if (mode == 1)      { vs = ((const long long*)ei)[e]; vd = ((const long long*)ei)[N_EDGES + e]; }
    else if (mode == 0) { vs = ((const int*)ei)[e];       vd = ((const int*)ei)[N_EDGES + e]; }
    else if (mode == 2) { vs = (long long)((const float*)ei)[e];  vd = (long long)((const float*)ei)[N_EDGES + e]; }
    else                { vs = (long long)((const double*)ei)[e]; vd = (long long)((const double*)ei)[N_EDGES + e]; }
    int s = (int)vs, d = (int)vd;
    if (s < 0) s = 0; if (s >= N_NODES) s = N_NODES - 1;
    if (d < 0) d = 0; if (d >= N_NODES) d = N_NODES - 1;
    atomicAdd(&g_dego[s], 1);
    int pos = atomicAdd(&g_degi[d], 1);
    if (pos < CAP) g_bkt[(size_t)d * CAP + pos] = s;
}

// ---------------- norms ------------------------------------------------------
__global__ void k_isqrt() {
    int i = blockIdx.x * blockDim.x + threadIdx.x;
    if (i >= N_NODES) return;
    g_iso[i] = rsqrtf((float)max(g_dego[i], 1));
    g_isi[i] = rsqrtf((float)max(g_degi[i], 1));
}

// ---------------- GEMM1 (tf32 MMA, smem-staged W1): h1 = x @ W1 -> fp16 -----
// PROVEN round-14 version. W1 tf32-rounded into [128][WPAD] smem once/block;
// B fragments via conflict-free LDS. Forked onto a side stream.
__global__ __launch_bounds__(256)
void k_gemm1_tf32(const float* __restrict__ x, const float* __restrict__ W) {
    extern __shared__ uint32_t Ws[];   // [128][WPAD] tf32 bits, 69.6 KB
    const int t = threadIdx.x;
    const int wid = t >> 5;
    const int lane = t & 31;

    #pragma unroll
    for (int i = 0; i < (IN_C * HID_C) / 256; i++) {
        int item = i * 256 + t;
        int kr = item >> 7, nc = item & 127;
        Ws[kr * WPAD + nc] = f2tf32(W[item]);
    }
    __syncthreads();

    const int row0 = blockIdx.x * 128 + wid * 16 + (lane >> 2);
    const int row1 = row0 + 8;
    const int rc0 = min(row0, N_NODES - 1);
    const int rc1 = min(row1, N_NODES - 1);
    const float* __restrict__ xr0 = x + (size_t)rc0 * IN_C + (lane & 3);
    const float* __restrict__ xr1 = x + (size_t)rc1 * IN_C + (lane & 3);

    float acc[16][4];
    #pragma unroll
    for (int n = 0; n < 16; n++)
        #pragma unroll
        for (int c = 0; c < 4; c++) acc[n][c] = 0.f;

    #pragma unroll 2
    for (int ks = 0; ks < 16; ks++) {
        const int k0 = ks * 8;
        uint32_t a0 = f2tf32(xr0[k0]);
        uint32_t a1 = f2tf32(xr1[k0]);
        uint32_t a2 = f2tf32(xr0[k0 + 4]);
        uint32_t a3 = f2tf32(xr1[k0 + 4]);
        const uint32_t* bb0 = Ws + (k0 + (lane & 3)) * WPAD + (lane >> 2);
        const uint32_t* bb1 = bb0 + 4 * WPAD;
        #pragma unroll
        for (int n = 0; n < 16; n++) {
            uint32_t b0 = bb0[n * 8];
            uint32_t b1 = bb1[n * 8];
            asm volatile(
                "mma.sync.aligned.m16n8k8.row.col.f32.tf32.tf32.f32 "
                "{%0,%1,%2,%3}, {%4,%5,%6,%7}, {%8,%9}, {%0,%1,%2,%3};"
                : "+f"(acc[n][0]), "+f"(acc[n][1]), "+f"(acc[n][2]), "+f"(acc[n][3])
                : "r"(a0), "r"(a1), "r"(a2), "r"(a3), "r"(b0), "r"(b1));
        }
    }

    const int colb = (lane & 3) * 2;
    #pragma unroll
    for (int n = 0; n < 16; n++) {
        int col = n * 8 + colb;
        if (row0 < N_NODES)
            *reinterpret_cast<__half2*>(g_h1h + (size_t)row0 * HID_C + col) =
                __floats2half2_rn(acc[n][0], acc[n][1]);
        if (row1 < N_NODES)
            *reinterpret_cast<__half2*>(g_h1h + (size_t)row1 * HID_C + col) =
                __floats2half2_rn(acc[n][2], acc[n][3]);
    }
}

// ---------------- FUSED: agg1 (fp16 rows, unroll-4) + relu/norm + MMA GEMM2 -
__global__ __launch_bounds__(WPB * 32)
void k_agg1_gemm2(const float* __restrict__ W2) {
    __shared__ uint32_t W2s[HID_C * OUT_C];        // 20 KB tf32 bits
    __shared__ uint32_t as_f[WPB * APAD];          // 8.25 KB tf32 bits [16][132]

    const int t = threadIdx.x;
    const int wid = t >> 5;
    const int lane = t & 31;
    const int base = blockIdx.x * WPB;

    #pragma unroll
    for (int i = 0; i < (HID_C * OUT_C) / (WPB * 32); i++)
        W2s[i * (WPB * 32) + t] = f2tf32(W2[i * (WPB * 32) + t]);

    // ---- gather phase (all 16 warps; 4 rows in flight) ----
    const int d = base + wid;
    const int* __restrict__ bp = g_bkt + (size_t)d * CAP;
    const int deg = min(g_degi[d], CAP);
    float4 acc0 = make_float4(0.f, 0.f, 0.f, 0.f);
    float4 acc1 = make_float4(0.f, 0.f, 0.f, 0.f);
    float4 acc2 = make_float4(0.f, 0.f, 0.f, 0.f);
    float4 acc3 = make_float4(0.f, 0.f, 0.f, 0.f);
    int j = 0;
    for (; j + 3 < deg; j += 4) {
        int s0 = bp[j], s1 = bp[j + 1], s2 = bp[j + 2], s3 = bp[j + 3];
        float f0 = g_iso[s0], f1 = g_iso[s1], f2 = g_iso[s2], f3 = g_iso[s3];
        uint2 u0 = *(reinterpret_cast<const uint2*>(g_h1h + (size_t)s0 * HID_C) + lane);
        uint2 u1 = *(reinterpret_cast<const uint2*>(g_h1h + (size_t)s1 * HID_C) + lane);
        uint2 u2 = *(reinterpret_cast<const uint2*>(g_h1h + (size_t)s2 * HID_C) + lane);
        uint2 u3 = *(reinterpret_cast<const uint2*>(g_h1h + (size_t)s3 * HID_C) + lane);
        float2 p0 = __half22float2(*reinterpret_cast<__half2*>(&u0.x));
        float2 q0 = __half22float2(*reinterpret_cast<__half2*>(&u0.y));
        float2 p1 = __half22float2(*reinterpret_cast<__half2*>(&u1.x));
        float2 q1 = __half22float2(*reinterpret_cast<__half2*>(&u1.y));
        float2 p2 = __half22float2(*reinterpret_cast<__half2*>(&u2.x));
        float2 q2 = __half22float2(*reinterpret_cast<__half2*>(&u2.y));
        float2 p3 = __half22float2(*reinterpret_cast<__half2*>(&u3.x));
        float2 q3 = __half22float2(*reinterpret_cast<__half2*>(&u3.y));
        acc0.x += f0 * p0.x; acc0.y += f0 * p0.y; acc0.z += f0 * q0.x; acc0.w += f0 * q0.y;
        acc1.x += f1 * p1.x; acc1.y += f1 * p1.y; acc1.z += f1 * q1.x; acc1.w += f1 * q1.y;
        acc2.x += f2 * p2.x; acc2.y += f2 * p2.y; acc2.z += f2 * q2.x; acc2.w += f2 * q2.y;
        acc3.x += f3 * p3.x; acc3.y += f3 * p3.y; acc3.z += f3 * q3.x; acc3.w += f3 * q3.y;
    }
    for (; j < deg; j++) {
        int s0 = bp[j];
        float f0 = g_iso[s0];
        uint2 u0 = *(reinterpret_cast<const uint2*>(g_h1h + (size_t)s0 * HID_C) + lane);
        float2 p0 = __half22float2(*reinterpret_cast<__half2*>(&u0.x));
        float2 q0 = __half22float2(*reinterpret_cast<__half2*>(&u0.y));
        acc0.x += f0 * p0.x; acc0.y += f0 * p0.y; acc0.z += f0 * q0.x; acc0.w += f0 * q0.y;
    }
    acc0.x += acc1.x + acc2.x + acc3.x;
    acc0.y += acc1.y + acc2.y + acc3.y;
    acc0.z += acc1.z + acc2.z + acc3.z;
    acc0.w += acc1.w + acc2.w + acc3.w;

    const float sc = g_iso[d] * g_isi[d];
    as_f[wid * APAD + lane * 4 + 0] = f2tf32(fmaxf(acc0.x, 0.f) * sc);
    as_f[wid * APAD + lane * 4 + 1] = f2tf32(fmaxf(acc0.y, 0.f) * sc);
    as_f[wid * APAD + lane * 4 + 2] = f2tf32(fmaxf(acc0.z, 0.f) * sc);
    as_f[wid * APAD + lane * 4 + 3] = f2tf32(fmaxf(acc0.w, 0.f) * sc);
    __syncthreads();

    // ---- MMA phase (warps 0..4, n-tile = wid) ----
    if (wid < 5) {
        const int nt = wid;
        float c0 = 0.f, c1 = 0.f, c2 = 0.f, c3 = 0.f;
        const uint32_t* __restrict__ ap0 = as_f + (lane >> 2) * APAD + (lane & 3);
        const uint32_t* __restrict__ ap1 = ap0 + 8 * APAD;
        const uint32_t* __restrict__ bb  = W2s + (lane & 3) * OUT_C + nt * 8 + (lane >> 2);
        #pragma unroll
        for (int ks = 0; ks < 16; ks++) {
            const int k0 = ks * 8;
            uint32_t a0 = ap0[k0];
            uint32_t a1 = ap1[k0];
            uint32_t a2 = ap0[k0 + 4];
            uint32_t a3 = ap1[k0 + 4];
            uint32_t b0 = bb[k0 * OUT_C];
            uint32_t b1 = bb[(k0 + 4) * OUT_C];
            asm volatile(
                "mma.sync.aligned.m16n8k8.row.col.f32.tf32.tf32.f32 "
                "{%0,%1,%2,%3}, {%4,%5,%6,%7}, {%8,%9}, {%0,%1,%2,%3};"
                : "+f"(c0), "+f"(c1), "+f"(c2), "+f"(c3)
                : "r"(a0), "r"(a1), "r"(a2), "r"(a3), "r"(b0), "r"(b1));
        }
        const int row0 = base + (lane >> 2);
        const int row1 = row0 + 8;
        const int col = nt * 8 + 2 * (lane & 3);
        *reinterpret_cast<__half2*>(g_th + (size_t)row0 * OUT_C + col) =
            __floats2half2_rn(c0, c1);
        *reinterpret_cast<__half2*>(g_th + (size_t)row1 * OUT_C + col) =
            __floats2half2_rn(c2, c3);
    }
}

// ---------------- gather 2: out[d] = isi[d]*sum g_t[s], 3 nodes/warp, x4 ----
__global__ __launch_bounds__(256)
void k_agg2(float* __restrict__ out) {
    int gw = (blockIdx.x * blockDim.x + threadIdx.x) >> 5;
    int lane = threadIdx.x & 31;
    int sub = lane / 10;                 // 0,1,2 (lanes 30,31 idle)
    int c = lane - sub * 10;             // 4-col chunk 0..9 (uint2 of halfs)
    int d = gw * 3 + sub;
    if (sub >= 3 || d >= N_NODES) return;
    const int* __restrict__ bp = g_bkt + (size_t)d * CAP;
    const int deg = min(g_degi[d], CAP);
    float4 acc0 = make_float4(0.f, 0.f, 0.f, 0.f);
    float4 acc1 = make_float4(0.f, 0.f, 0.f, 0.f);
    float4 acc2 = make_float4(0.f, 0.f, 0.f, 0.f);
    float4 acc3 = make_float4(0.f, 0.f, 0.f, 0.f);
    int j = 0;
    for (; j + 3 < deg; j += 4) {
        int s0 = bp[j], s1 = bp[j + 1], s2 = bp[j + 2], s3 = bp[j + 3];
        uint2 u0 = *(reinterpret_cast<const uint2*>(g_th + (size_t)s0 * OUT_C) + c);
        uint2 u1 = *(reinterpret_cast<const uint2*>(g_th + (size_t)s1 * OUT_C) + c);
        uint2 u2 = *(reinterpret_cast<const uint2*>(g_th + (size_t)s2 * OUT_C) + c);
        uint2 u3 = *(reinterpret_cast<const uint2*>(g_th + (size_t)s3 * OUT_C) + c);
        float2 p0 = __half22float2(*reinterpret_cast<__half2*>(&u0.x));
        float2 q0 = __half22float2(*reinterpret_cast<__half2*>(&u0.y));
        float2 p1 = __half22float2(*reinterpret_cast<__half2*>(&u1.x));
        float2 q1 = __half22float2(*reinterpret_cast<__half2*>(&u1.y));
        float2 p2 = __half22float2(*reinterpret_cast<__half2*>(&u2.x));
        float2 q2 = __half22float2(*reinterpret_cast<__half2*>(&u2.y));
        float2 p3 = __half22float2(*reinterpret_cast<__half2*>(&u3.x));
        float2 q3 = __half22float2(*reinterpret_cast<__half2*>(&u3.y));
        acc0.x += p0.x; acc0.y += p0.y; acc0.z += q0.x; acc0.w += q0.y;
        acc1.x += p1.x; acc1.y += p1.y; acc1.z += q1.x; acc1.w += q1.y;
        acc2.x += p2.x; acc2.y += p2.y; acc2.z += q2.x; acc2.w += q2.y;
        acc3.x += p3.x; acc3.y += p3.y; acc3.z += q3.x; acc3.w += q3.y;
    }
    for (; j < deg; j++) {
        int s0 = bp[j];
        uint2 u0 = *(reinterpret_cast<const uint2*>(g_th + (size_t)s0 * OUT_C) + c);
        float2 p0 = __half22float2(*reinterpret_cast<__half2*>(&u0.x));
        float2 q0 = __half22float2(*reinterpret_cast<__half2*>(&u0.y));
        acc0.x += p0.x; acc0.y += p0.y; acc0.z += q0.x; acc0.w += q0.y;
    }
    float sc = g_isi[d];
    acc0.x = (acc0.x + acc1.x + acc2.x + acc3.x) * sc;
    acc0.y = (acc0.y + acc1.y + acc2.y + acc3.y) * sc;
    acc0.z = (acc0.z + acc1.z + acc2.z + acc3.z) * sc;
    acc0.w = (acc0.w + acc1.w + acc2.w + acc3.w) * sc;
    *reinterpret_cast<float4*>(out + (size_t)d * OUT_C + c * 4) = acc0;
}

// ---------------- launch ----------------------------------------------------
extern "C" void kernel_launch(void* const* d_in, const int* in_sizes, int n_in,
                              void* d_out, int out_size) {
    const float* x  = (const float*)d_in[0];
    const void*  ei = d_in[1];
    const float* W1 = (const float*)d_in[2];
    const float* W2 = (const float*)d_in[3];
    float* out = (float*)d_out;

    // One-time side-stream / event setup (no device memory; capture-legal)
    static cudaStream_t s_side = nullptr;
    static cudaEvent_t ev_fork = nullptr, ev_join = nullptr;
    static int smem_cfg = 0;
    const int smem1 = IN_C * WPAD * 4;   // 69632 B
    if (!s_side) {
        cudaStreamCreateWithFlags(&s_side, cudaStreamNonBlocking);
        cudaEventCreateWithFlags(&ev_fork, cudaEventDisableTiming);
        cudaEventCreateWithFlags(&ev_join, cudaEventDisableTiming);
    }
    if (!smem_cfg) {
        cudaFuncSetAttribute(k_gemm1_tf32,
                             cudaFuncAttributeMaxDynamicSharedMemorySize, smem1);
        smem_cfg = 1;
    }

    // Fork: GEMM1 (x @ W1) on the side stream
    cudaEventRecord(ev_fork, 0);
    cudaStreamWaitEvent(s_side, ev_fork, 0);
    k_gemm1_tf32<<<GEMM1_BLOCKS, 256, smem1, s_side>>>(x, W1);
    cudaEventRecord(ev_join, s_side);

    // Main stream: zero+detect -> one-pass decode/histogram/bucket-fill -> norms
    k_zero_detect<<<(N_NODES + 255) / 256, 256>>>((const int*)ei);
    k_convert_fill<<<(N_EDGES + 255) / 256, 256>>>(ei);
    k_isqrt<<<(N_NODES + 255) / 256, 256>>>();

    // Join: fused aggregation needs both h1 and the buckets
    cudaStreamWaitEvent(0, ev_join, 0);

    k_agg1_gemm2<<<N_NODES / WPB, WPB * 32>>>(W2);

    {
        int warps = (N_NODES + 2) / 3;
        int blocks = (warps * 32 + 255) / 256;
        k_agg2<<<blocks, 256>>>(out);
    }
}

// round 17
// speedup vs baseline: 1.1185x; 1.0212x over previous
#include <cuda_runtime.h>
#include <cuda_bf16.h>
#include <cuda_fp16.h>
#include <cstdint>

// Problem dims — FIXED by the dataset (reference hardcodes them).
#define N_NODES 100000
#define N_EDGES 1600000
#define IN_C    128
#define HID_C   128
#define OUT_C   40

#define NPB2    32    // nodes per block in fused agg kernel (100000 % 32 == 0)
#define WPAD    136   // padded W1 row stride (floats) -> conflict-free B frags
#define APAD    132   // padded as row stride -> conflict-free A frags
#define GEMM1_BLOCKS ((N_NODES + 127) / 128)   // 782
#define CAP     96    // bucket capacity per node (P(deg>=96) < 1e-40)

// ---------------- scratch (static __device__ globals; no allocation) --------
__device__ __half g_h1h[(size_t)N_NODES * HID_C]; // 25.6 MB: x @ W1 (fp16)
__device__ __half g_th [(size_t)N_NODES * OUT_C]; // 8 MB: layer-2 proj (fp16)
__device__ int    g_bkt[(size_t)N_NODES * CAP];   // 38.4 MB: src ids per dst
__device__ int    g_degi[N_NODES];                // in-degree (= fill cursor)
__device__ int    g_dego[N_NODES];                // out-degree
__device__ float  g_iso[N_NODES];                 // out-degree^{-1/2}
__device__ float  g_isi[N_NODES];                 // in-degree^{-1/2}
__device__ int    g_mode;                         // edge dtype

// ---------------- helpers ----------------------------------------------------
__device__ __forceinline__ uint32_t f2tf32(float v) {
    uint32_t r;
    asm("cvt.rna.tf32.f32 %0, %1;" : "=r"(r) : "f"(v));
    return r;
}

// ---------------- zero + dtype probe (fused) ---------------------------------
__global__ void k_zero_detect(const int* __restrict__ w32) {
    int i = blockIdx.x * blockDim.x + threadIdx.x;
    if (i < N_NODES) { g_degi[i] = 0; g_dego[i] = 0; }
    if (i == 0) {
        int oz = 0, ez = 0, ir = 0;
        for (int k = 0; k < 512; k++) {
            int w = w32[k];
            if (w == 0) { if (k & 1) oz++; else ez++; }
            if (w >= 0 && w < N_NODES) ir++;
        }
        int mode;
        if (oz > 240)      mode = 1;   // int64
        else if (ez > 240) mode = 3;   // float64
        else if (ir > 500) mode = 0;   // int32
        else               mode = 2;   // float32
        g_mode = mode;
    }
}

// ---------------- ONE PASS: decode + out-degree histogram + bucket fill ------
__global__ void k_convert_fill(const void* __restrict__ ei) {
    int e = blockIdx.x * blockDim.x + threadIdx.x;
    if (e >= N_EDGES) return;
    const int mode = g_mode;
    long long vs, vd;
    if (mode == 1)      { vs = ((const long long*)ei)[e]; vd = ((const long long*)ei)[N_EDGES + e]; }
    else if (mode == 0) { vs = ((const int*)ei)[e];       vd = ((const int*)ei)[N_EDGES + e]; }
    else if (mode == 2) { vs = (long long)((const float*)ei)[e];  vd = (long long)((const float*)ei)[N_EDGES + e]; }
    else                { vs = (long long)((const double*)ei)[e]; vd = (long long)((const double*)ei)[N_EDGES + e]; }
    int s = (int)vs, d = (int)vd;
    if (s < 0) s = 0; if (s >= N_NODES) s = N_NODES - 1;
    if (d < 0) d = 0; if (d >= N_NODES) d = N_NODES - 1;
    atomicAdd(&g_dego[s], 1);
    int pos = atomicAdd(&g_degi[d], 1);
    if (pos < CAP) g_bkt[(size_t)d * CAP + pos] = s;
}

// ---------------- norms ------------------------------------------------------
__global__ void k_isqrt() {
    int i = blockIdx.x * blockDim.x + threadIdx.x;
    if (i >= N_NODES) return;
    g_iso[i] = rsqrtf((float)max(g_dego[i], 1));
    g_isi[i] = rsqrtf((float)max(g_degi[i], 1));
}

// ---------------- GEMM1 (tf32 MMA, smem-staged W1): h1 = x @ W1 -> fp16 -----
// PROVEN round-14 version, untouched. Forked onto a side stream.
__global__ __launch_bounds__(256)
void k_gemm1_tf32(const float* __restrict__ x, const float* __restrict__ W) {
    extern __shared__ uint32_t Ws[];   // [128][WPAD] tf32 bits, 69.6 KB
    const int t = threadIdx.x;
    const int wid = t >> 5;
    const int lane = t & 31;

    #pragma unroll
    for (int i = 0; i < (IN_C * HID_C) / 256; i++) {
        int item = i * 256 + t;
        int kr = item >> 7, nc = item & 127;
        Ws[kr * WPAD + nc] = f2tf32(W[item]);
    }
    __syncthreads();

    const int row0 = blockIdx.x * 128 + wid * 16 + (lane >> 2);
    const int row1 = row0 + 8;
    const int rc0 = min(row0, N_NODES - 1);
    const int rc1 = min(row1, N_NODES - 1);
    const float* __restrict__ xr0 = x + (size_t)rc0 * IN_C + (lane & 3);
    const float* __restrict__ xr1 = x + (size_t)rc1 * IN_C + (lane & 3);

    float acc[16][4];
    #pragma unroll
    for (int n = 0; n < 16; n++)
        #pragma unroll
        for (int c = 0; c < 4; c++) acc[n][c] = 0.f;

    #pragma unroll 2
    for (int ks = 0; ks < 16; ks++) {
        const int k0 = ks * 8;
        uint32_t a0 = f2tf32(xr0[k0]);
        uint32_t a1 = f2tf32(xr1[k0]);
        uint32_t a2 = f2tf32(xr0[k0 + 4]);
        uint32_t a3 = f2tf32(xr1[k0 + 4]);
        const uint32_t* bb0 = Ws + (k0 + (lane & 3)) * WPAD + (lane >> 2);
        const uint32_t* bb1 = bb0 + 4 * WPAD;
        #pragma unroll
        for (int n = 0; n < 16; n++) {
            uint32_t b0 = bb0[n * 8];
            uint32_t b1 = bb1[n * 8];
            asm volatile(
                "mma.sync.aligned.m16n8k8.row.col.f32.tf32.tf32.f32 "
                "{%0,%1,%2,%3}, {%4,%5,%6,%7}, {%8,%9}, {%0,%1,%2,%3};"
                : "+f"(acc[n][0]), "+f"(acc[n][1]), "+f"(acc[n][2]), "+f"(acc[n][3])
                : "r"(a0), "r"(a1), "r"(a2), "r"(a3), "r"(b0), "r"(b1));
        }
    }

    const int colb = (lane & 3) * 2;
    #pragma unroll
    for (int n = 0; n < 16; n++) {
        int col = n * 8 + colb;
        if (row0 < N_NODES)
            *reinterpret_cast<__half2*>(g_h1h + (size_t)row0 * HID_C + col) =
                __floats2half2_rn(acc[n][0], acc[n][1]);
        if (row1 < N_NODES)
            *reinterpret_cast<__half2*>(g_h1h + (size_t)row1 * HID_C + col) =
                __floats2half2_rn(acc[n][2], acc[n][3]);
    }
}

// ---------------- FUSED: agg1 (2 nodes/warp) + relu/norm + MMA GEMM2 --------
// 16 warps x 2 nodes = 32 nodes per block. Predicated dual-node gather loop
// keeps MLP-2 while halving barrier straggler variance (Poisson(32) vs (16)).
// MMA phase: 10 warps = 2 row-tiles x 5 n-tiles.
__global__ __launch_bounds__(512)
void k_agg1_gemm2(const float* __restrict__ W2) {
    __shared__ uint32_t W2s[HID_C * OUT_C];        // 20 KB tf32 bits
    __shared__ uint32_t as_f[NPB2 * APAD];         // 16.9 KB tf32 bits [32][132]

    const int t = threadIdx.x;
    const int wid = t >> 5;
    const int lane = t & 31;
    const int base = blockIdx.x * NPB2;

    #pragma unroll
    for (int i = 0; i < (HID_C * OUT_C) / 512; i++)
        W2s[i * 512 + t] = f2tf32(W2[i * 512 + t]);

    // ---- gather phase: warp handles nodes dA = base+2w, dB = dA+1 ----
    const int dA = base + wid * 2;
    const int dB = dA + 1;
    const int* __restrict__ bpA = g_bkt + (size_t)dA * CAP;
    const int* __restrict__ bpB = g_bkt + (size_t)dB * CAP;
    const int degA = min(g_degi[dA], CAP);
    const int degB = min(g_degi[dB], CAP);
    float4 accA = make_float4(0.f, 0.f, 0.f, 0.f);
    float4 accB = make_float4(0.f, 0.f, 0.f, 0.f);
    const int m = degA > degB ? degA : degB;
    for (int j = 0; j < m; j++) {
        if (j < degA) {
            int s = bpA[j];                        // warp-uniform
            float f = g_iso[s];
            uint2 u = *(reinterpret_cast<const uint2*>(g_h1h + (size_t)s * HID_C) + lane);
            float2 p = __half22float2(*reinterpret_cast<__half2*>(&u.x));
            float2 q = __half22float2(*reinterpret_cast<__half2*>(&u.y));
            accA.x += f * p.x; accA.y += f * p.y; accA.z += f * q.x; accA.w += f * q.y;
        }
        if (j < degB) {
            int s = bpB[j];
            float f = g_iso[s];
            uint2 u = *(reinterpret_cast<const uint2*>(g_h1h + (size_t)s * HID_C) + lane);
            float2 p = __half22float2(*reinterpret_cast<__half2*>(&u.x));
            float2 q = __half22float2(*reinterpret_cast<__half2*>(&u.y));
            accB.x += f * p.x; accB.y += f * p.y; accB.z += f * q.x; accB.w += f * q.y;
        }
    }

    const float scA = g_iso[dA] * g_isi[dA];
    const float scB = g_iso[dB] * g_isi[dB];
    uint32_t* rA = as_f + (wid * 2) * APAD + lane * 4;
    uint32_t* rB = rA + APAD;
    rA[0] = f2tf32(fmaxf(accA.x, 0.f) * scA);
    rA[1] = f2tf32(fmaxf(accA.y, 0.f) * scA);
    rA[2] = f2tf32(fmaxf(accA.z, 0.f) * scA);
    rA[3] = f2tf32(fmaxf(accA.w, 0.f) * scA);
    rB[0] = f2tf32(fmaxf(accB.x, 0.f) * scB);
    rB[1] = f2tf32(fmaxf(accB.y, 0.f) * scB);
    rB[2] = f2tf32(fmaxf(accB.z, 0.f) * scB);
    rB[3] = f2tf32(fmaxf(accB.w, 0.f) * scB);
    __syncthreads();

    // ---- MMA phase (warps 0..9: tile = wid/5 in {0,1}, n-tile = wid%5) ----
    if (wid < 10) {
        const int tile = wid / 5;
        const int nt = wid % 5;
        float c0 = 0.f, c1 = 0.f, c2 = 0.f, c3 = 0.f;
        const uint32_t* __restrict__ ap0 =
            as_f + (tile * 16 + (lane >> 2)) * APAD + (lane & 3);
        const uint32_t* __restrict__ ap1 = ap0 + 8 * APAD;
        const uint32_t* __restrict__ bb  = W2s + (lane & 3) * OUT_C + nt * 8 + (lane >> 2);
        #pragma unroll
        for (int ks = 0; ks < 16; ks++) {
            const int k0 = ks * 8;
            uint32_t a0 = ap0[k0];
            uint32_t a1 = ap1[k0];
            uint32_t a2 = ap0[k0 + 4];
            uint32_t a3 = ap1[k0 + 4];
            uint32_t b0 = bb[k0 * OUT_C];
            uint32_t b1 = bb[(k0 + 4) * OUT_C];
            asm volatile(
                "mma.sync.aligned.m16n8k8.row.col.f32.tf32.tf32.f32 "
                "{%0,%1,%2,%3}, {%4,%5,%6,%7}, {%8,%9}, {%0,%1,%2,%3};"
                : "+f"(c0), "+f"(c1), "+f"(c2), "+f"(c3)
                : "r"(a0), "r"(a1), "r"(a2), "r"(a3), "r"(b0), "r"(b1));
        }
        const int row0 = base + tile * 16 + (lane >> 2);
        const int row1 = row0 + 8;
        const int col = nt * 8 + 2 * (lane & 3);
        *reinterpret_cast<__half2*>(g_th + (size_t)row0 * OUT_C + col) =
            __floats2half2_rn(c0, c1);
        *reinterpret_cast<__half2*>(g_th + (size_t)row1 * OUT_C + col) =
            __floats2half2_rn(c2, c3);
    }
}

// ---------------- gather 2: out[d] = isi[d]*sum g_t[s], 3 nodes/warp, x2 ----
__global__ __launch_bounds__(256)
void k_agg2(float* __restrict__ out) {
    int gw = (blockIdx.x * blockDim.x + threadIdx.x) >> 5;
    int lane = threadIdx.x & 31;
    int sub = lane / 10;                 // 0,1,2 (lanes 30,31 idle)
    int c = lane - sub * 10;             // 4-col chunk 0..9 (uint2 of halfs)
    int d = gw * 3 + sub;
    if (sub >= 3 || d >= N_NODES) return;
    const int* __restrict__ bp = g_bkt + (size_t)d * CAP;
    const int deg = min(g_degi[d], CAP);
    float4 acc  = make_float4(0.f, 0.f, 0.f, 0.f);
    float4 accB = make_float4(0.f, 0.f, 0.f, 0.f);
    int j = 0;
    for (; j + 1 < deg; j += 2) {
        int s0 = bp[j], s1 = bp[j + 1];
        uint2 u0 = *(reinterpret_cast<const uint2*>(g_th + (size_t)s0 * OUT_C) + c);
        uint2 u1 = *(reinterpret_cast<const uint2*>(g_th + (size_t)s1 * OUT_C) + c);
        float2 p0 = __half22float2(*reinterpret_cast<__half2*>(&u0.x));
        float2 q0 = __half22float2(*reinterpret_cast<__half2*>(&u0.y));
        float2 p1 = __half22float2(*reinterpret_cast<__half2*>(&u1.x));
        float2 q1 = __half22float2(*reinterpret_cast<__half2*>(&u1.y));
        acc.x  += p0.x; acc.y  += p0.y; acc.z  += q0.x; acc.w  += q0.y;
        accB.x += p1.x; accB.y += p1.y; accB.z += q1.x; accB.w += q1.y;
    }
    if (j < deg) {
        int s0 = bp[j];
        uint2 u0 = *(reinterpret_cast<const uint2*>(g_th + (size_t)s0 * OUT_C) + c);
        float2 p0 = __half22float2(*reinterpret_cast<__half2*>(&u0.x));
        float2 q0 = __half22float2(*reinterpret_cast<__half2*>(&u0.y));
        acc.x += p0.x; acc.y += p0.y; acc.z += q0.x; acc.w += q0.y;
    }
    float sc = g_isi[d];
    acc.x = (acc.x + accB.x) * sc;
    acc.y = (acc.y + accB.y) * sc;
    acc.z = (acc.z + accB.z) * sc;
    acc.w = (acc.w + accB.w) * sc;
    *reinterpret_cast<float4*>(out + (size_t)d * OUT_C + c * 4) = acc;
}

// ---------------- launch ----------------------------------------------------
extern "C" void kernel_launch(void* const* d_in, const int* in_sizes, int n_in,
                              void* d_out, int out_size) {
    const float* x  = (const float*)d_in[0];
    const void*  ei = d_in[1];
    const float* W1 = (const float*)d_in[2];
    const float* W2 = (const float*)d_in[3];
    float* out = (float*)d_out;

    // One-time side-stream / event setup (no device memory; capture-legal)
    static cudaStream_t s_side = nullptr;
    static cudaEvent_t ev_fork = nullptr, ev_join = nullptr;
    static int smem_cfg = 0;
    const int smem1 = IN_C * WPAD * 4;   // 69632 B
    if (!s_side) {
        cudaStreamCreateWithFlags(&s_side, cudaStreamNonBlocking);
        cudaEventCreateWithFlags(&ev_fork, cudaEventDisableTiming);
        cudaEventCreateWithFlags(&ev_join, cudaEventDisableTiming);
    }
    if (!smem_cfg) {
        cudaFuncSetAttribute(k_gemm1_tf32,
                             cudaFuncAttributeMaxDynamicSharedMemorySize, smem1);
        smem_cfg = 1;
    }

    // Fork: GEMM1 (x @ W1) on the side stream
    cudaEventRecord(ev_fork, 0);
    cudaStreamWaitEvent(s_side, ev_fork, 0);
    k_gemm1_tf32<<<GEMM1_BLOCKS, 256, smem1, s_side>>>(x, W1);
    cudaEventRecord(ev_join, s_side);

    // Main stream: zero+detect -> one-pass decode/histogram/bucket-fill -> norms
    k_zero_detect<<<(N_NODES + 255) / 256, 256>>>((const int*)ei);
    k_convert_fill<<<(N_EDGES + 255) / 256, 256>>>(ei);
    k_isqrt<<<(N_NODES + 255) / 256, 256>>>();

    // Join: fused aggregation needs both h1 and the buckets
    cudaStreamWaitEvent(0, ev_join, 0);

    k_agg1_gemm2<<<N_NODES / NPB2, 512>>>(W2);

    {
        int warps = (N_NODES + 2) / 3;
        int blocks = (warps * 32 + 255) / 256;
        k_agg2<<<blocks, 256>>>(out);
    }
}